// round 17
// baseline (speedup 1.0000x reference)
#include <cuda_runtime.h>
#include <cuda_fp16.h>
#include <cstdint>
#include <math.h>

// ---------------------------------------------------------------------------
// GRU cell, legacy mma path (tcgen05 rejected by harness PTX target sm_103).
// R17: R16 + producers chained to virtual KT=64 (two adjacent col tiles per
// block, col switch at kt=32 with acc stash — same handoff trick the consumer
// z-segment uses). Grid 2048 -> 1536 blocks; every block now runs the proven
// KT=64 amortization point (measured packing: KT=16 39.7%, KT=32 ~47%,
// KT=64 ~52-53%).
//   blocks   0..511  : r-gate, 2 tiles (cols c..c+255), K=2048 each
//   blocks 512..1535 : chained z/hp/p2 (virtual KT=64), blend epilogue
// Mainloop config unchanged: 128x128 tile, 8 warps 64x32, BK=64, NST=3,
// single barrier/iter, fp16 ldmatrix+mma, 2 CTA/SM.
// ---------------------------------------------------------------------------

#define BATCH   16384
#define HID     1024
#define KCAT    2048
#define BK      64            // k halves per stage (4 x k16 MMA steps)
#define NST     3

#define BM 128
#define BN 128
#define RS 72                               // smem row stride in halves (144 B)
#define A_STAGE_B (BM * RS * 2)             // 18432 B
#define B_STAGE_B (BN * RS * 2)             // 18432 B
#define STAGE_B   (A_STAGE_B + B_STAGE_B)   // 36864 B
#define SMEM_TOTAL (NST * STAGE_B)          // 110592 B (x2 CTAs <= 228 KB)

#define KT_TOT 64
#define KB_HP  32             // consumer: hp segment start / producer: col switch
#define KB_P2  48             // consumer: g_rh segment start

#define NPANEL 128
#define NBLK_R 512            // producer blocks (2 r-gate tiles each)
#define NBLK   1536

// -------------------------- device scratch ---------------------------------
__device__ __half g_A [BATCH * KCAT];
__device__ __half g_Wt[3][HID * KCAT];   // [n][k]
__device__ __half g_rh[BATCH * HID];
__device__ __half g_z [BATCH * HID];
__device__ unsigned g_flag[NPANEL];

// -------------------------- helpers ----------------------------------------
__device__ __forceinline__ void mma_f16(float* c, const uint32_t* a, const uint32_t* b) {
    asm volatile(
        "mma.sync.aligned.m16n8k16.row.col.f32.f16.f16.f32 "
        "{%0,%1,%2,%3}, {%4,%5,%6,%7}, {%8,%9}, {%0,%1,%2,%3};\n"
        : "+f"(c[0]), "+f"(c[1]), "+f"(c[2]), "+f"(c[3])
        : "r"(a[0]), "r"(a[1]), "r"(a[2]), "r"(a[3]),
          "r"(b[0]), "r"(b[1]));
}
__device__ __forceinline__ void ldsm4(uint32_t* r, uint32_t addr) {
    asm volatile("ldmatrix.sync.aligned.m8n8.x4.shared.b16 {%0,%1,%2,%3}, [%4];"
                 : "=r"(r[0]), "=r"(r[1]), "=r"(r[2]), "=r"(r[3]) : "r"(addr));
}
__device__ __forceinline__ void cp16u(uint32_t smem_dst, const void* gmem_src) {
    asm volatile("cp.async.cg.shared.global [%0], [%1], 16;" :: "r"(smem_dst), "l"(gmem_src));
}
__device__ __forceinline__ void cp_commit() { asm volatile("cp.async.commit_group;"); }
template <int N>
__device__ __forceinline__ void cp_wait() { asm volatile("cp.async.wait_group %0;" :: "n"(N) : "memory"); }
__device__ __forceinline__ float sigmoidf_fast(float v) { return 1.0f / (1.0f + __expf(-v)); }
__device__ __forceinline__ float tanhf_fast(float v) {
    return 1.0f - 2.0f / (__expf(2.0f * v) + 1.0f);
}

// ---------------------------------------------------------------------------
// Init + prep kernels
// ---------------------------------------------------------------------------
__global__ void init_kernel() {
    if (threadIdx.x < NPANEL) g_flag[threadIdx.x] = 0;
}

__global__ void prep_concat_kernel(const float* __restrict__ h,
                                   const float* __restrict__ x)
{
    size_t n8 = (size_t)BATCH * KCAT / 8;
    for (size_t i = (size_t)blockIdx.x * blockDim.x + threadIdx.x;
         i < n8; i += (size_t)gridDim.x * blockDim.x) {
        size_t e   = i * 8;
        size_t row = e >> 11;
        size_t col = e & (KCAT - 1);
        const float* src = (col < HID) ? (h + row * HID + col)
                                       : (x + row * HID + (col - HID));
        float4 v0 = ((const float4*)src)[0];
        float4 v1 = ((const float4*)src)[1];
        __half2 o[4];
        o[0] = __float22half2_rn(make_float2(v0.x, v0.y));
        o[1] = __float22half2_rn(make_float2(v0.z, v0.w));
        o[2] = __float22half2_rn(make_float2(v1.x, v1.y));
        o[3] = __float22half2_rn(make_float2(v1.z, v1.w));
        ((uint4*)g_A)[i] = *(uint4*)o;
    }
}

__global__ void prep_weights_kernel(const float* __restrict__ Wr,
                                    const float* __restrict__ Wz,
                                    const float* __restrict__ Wh)
{
    __shared__ float t[32][33];
    const float* src = (blockIdx.z == 0) ? Wr : (blockIdx.z == 1) ? Wz : Wh;
    __half* dst = g_Wt[blockIdx.z];
    int tx = threadIdx.x, ty = threadIdx.y;
    int c0 = blockIdx.x * 32;   // n
    int r0 = blockIdx.y * 32;   // k
    #pragma unroll
    for (int j = 0; j < 32; j += 8)
        t[ty + j][tx] = src[(size_t)(r0 + ty + j) * HID + c0 + tx];
    __syncthreads();
    #pragma unroll
    for (int j = 0; j < 32; j += 8)
        dst[(size_t)(c0 + ty + j) * KCAT + r0 + tx] = __float2half_rn(t[tx][ty + j]);
}

// ---------------------------------------------------------------------------
// Fused GEMM kernel: blockIdx-ordered producer/consumer dispatch, KT=64 both.
// ---------------------------------------------------------------------------
__global__ void __launch_bounds__(256, 2)
gru_all(const float* __restrict__ h, float* __restrict__ out)
{
    extern __shared__ char smem[];
    const uint32_t sbase = (uint32_t)__cvta_generic_to_shared(smem);
    const int tid    = threadIdx.x;
    const int lane   = tid & 31;
    const int wid    = tid >> 5;
    const int warp_m = wid >> 2;         // 0..1 -> 64-row band
    const int warp_n = wid & 3;          // 0..3 -> 32-col band
    const int bid    = blockIdx.x;

    const bool is_r = (bid < NBLK_R);
    int panel, colbase;
    if (is_r) {
        panel   = bid >> 2;              // 4 producer blocks per panel
        colbase = (bid & 3) << 8;        // tile 0 at colbase, tile 1 at +128
    } else {
        const int lbid = bid - NBLK_R;
        panel   = lbid >> 3;
        colbase = (lbid & 7) << 7;       // single col tile
    }
    const int row0 = panel << 7;

    // per-thread ldmatrix base offsets (bytes within stage)
    uint32_t a_off[4];
    #pragma unroll
    for (int mt = 0; mt < 4; mt++)
        a_off[mt] = (warp_m * 64 + mt * 16 + (lane & 15)) * (RS * 2)
                  + ((lane >> 4) & 1) * 16;
    uint32_t b_off[2];
    #pragma unroll
    for (int nt2 = 0; nt2 < 2; nt2++)
        b_off[nt2] = A_STAGE_B
                   + (warp_n * 32 + nt2 * 16 + (lane & 7) + ((lane >> 4) & 1) * 8) * (RS * 2)
                   + ((lane >> 3) & 1) * 16;

    // virtual-kt -> operands
    auto load_stage = [&](int kt) {
        const uint32_t so = sbase + (kt % NST) * STAGE_B;
        const __half* Amat;
        const __half* Bmat;
        int astride, kbase, bcol;
        if (is_r) {
            Amat = g_A;  astride = KCAT; kbase = (kt & 31) * BK;
            Bmat = g_Wt[0];
            bcol = colbase + ((kt >= KB_HP) ? 128 : 0);
        } else if (kt < KB_HP) {
            Amat = g_A;  astride = KCAT; kbase = kt * BK;
            Bmat = g_Wt[1]; bcol = colbase;
        } else if (kt < KB_P2) {
            Amat = g_A;  astride = KCAT; kbase = (kt - 16) * BK;   // 1024 + (kt-32)*64
            Bmat = g_Wt[2]; bcol = colbase;
        } else {
            Amat = g_rh; astride = HID;  kbase = (kt - KB_P2) * BK;
            Bmat = g_Wt[2]; bcol = colbase;
        }
        #pragma unroll
        for (int j = 0; j < 4; j++) {
            int idx = tid + j * 256;
            int r = idx >> 3, c = idx & 7;
            cp16u(so + r * (RS * 2) + c * 16,
                  Amat + (size_t)(row0 + r) * astride + kbase + c * 8);
        }
        #pragma unroll
        for (int j = 0; j < 4; j++) {
            int idx = tid + j * 256;
            int r = idx >> 3, c = idx & 7;
            cp16u(so + A_STAGE_B + r * (RS * 2) + c * 16,
                  Bmat + (size_t)(bcol + r) * KCAT + kbase + c * 8);
        }
        cp_commit();
    };

    float acc[4][4][4];
    #pragma unroll
    for (int mt = 0; mt < 4; mt++)
        #pragma unroll
        for (int nt = 0; nt < 4; nt++)
            #pragma unroll
            for (int i = 0; i < 4; i++)
                acc[mt][nt][i] = 0.0f;

    load_stage(0);
    load_stage(1);

    for (int kt = 0; kt < KT_TOT; kt++) {
        if (kt < KT_TOT - 1) cp_wait<1>(); else cp_wait<0>();
        __syncthreads();                 // single barrier per iteration
        if (kt + 2 < KT_TOT) {
            // consumers: gate the FIRST prefetch that touches g_rh on the
            // per-panel producer flag (8 tiles). Producers sit >=512+4p blocks
            // earlier in schedule order -> near-zero spin.
            if (!is_r && (kt + 2) == KB_P2) {
                if (tid == 0) {
                    volatile unsigned* f = &g_flag[panel];
                    while (*f < 8u) __nanosleep(64);
                }
                __syncthreads();
                __threadfence();         // acquire
            }
            load_stage(kt + 2);
        }

        if (kt == KB_HP) {
            if (is_r) {
                // producer handoff: emit tile 0 (cols colbase..+127) -> g_rh,
                // zero acc, continue with tile 1.
                #pragma unroll
                for (int mt = 0; mt < 4; mt++) {
                    #pragma unroll
                    for (int nt = 0; nt < 4; nt++) {
                        int r = row0 + warp_m * 64 + mt * 16 + (lane >> 2);
                        int c = colbase + warp_n * 32 + nt * 8 + (lane & 3) * 2;
                        #pragma unroll
                        for (int half_i = 0; half_i < 2; half_i++) {
                            size_t gi = (size_t)(r + half_i * 8) * HID + c;
                            float v0 = acc[mt][nt][half_i * 2 + 0];
                            float v1 = acc[mt][nt][half_i * 2 + 1];
                            float2 hv = *(const float2*)(h + gi);
                            *(__half2*)(g_rh + gi) = __float22half2_rn(make_float2(
                                sigmoidf_fast(v0) * hv.x, sigmoidf_fast(v1) * hv.y));
                            acc[mt][nt][half_i * 2 + 0] = 0.0f;
                            acc[mt][nt][half_i * 2 + 1] = 0.0f;
                        }
                    }
                }
            } else {
                // consumer z handoff: stash sigmoid(acc) -> g_z, zero acc.
                #pragma unroll
                for (int mt = 0; mt < 4; mt++) {
                    #pragma unroll
                    for (int nt = 0; nt < 4; nt++) {
                        int r = row0 + warp_m * 64 + mt * 16 + (lane >> 2);
                        int c = colbase + warp_n * 32 + nt * 8 + (lane & 3) * 2;
                        #pragma unroll
                        for (int half_i = 0; half_i < 2; half_i++) {
                            size_t gi = (size_t)(r + half_i * 8) * HID + c;
                            *(__half2*)(g_z + gi) = __float22half2_rn(make_float2(
                                sigmoidf_fast(acc[mt][nt][half_i * 2 + 0]),
                                sigmoidf_fast(acc[mt][nt][half_i * 2 + 1])));
                            acc[mt][nt][half_i * 2 + 0] = 0.0f;
                            acc[mt][nt][half_i * 2 + 1] = 0.0f;
                        }
                    }
                }
            }
        }

        const uint32_t so = sbase + (kt % NST) * STAGE_B;
        #pragma unroll
        for (int ks = 0; ks < 4; ks++) {     // four k16 steps per stage
            uint32_t a[4][4], b[2][4];
            #pragma unroll
            for (int mt = 0; mt < 4; mt++)
                ldsm4(a[mt], so + a_off[mt] + ks * 32);
            #pragma unroll
            for (int nt2 = 0; nt2 < 2; nt2++)
                ldsm4(b[nt2], so + b_off[nt2] + ks * 32);
            #pragma unroll
            for (int mt = 0; mt < 4; mt++)
                #pragma unroll
                for (int nt = 0; nt < 4; nt++)
                    mma_f16(acc[mt][nt], a[mt], &b[nt >> 1][(nt & 1) * 2]);
        }
        // no trailing barrier: 3-deep ring; next write to this slot is gated
        // by the next top-of-loop barrier.
    }

    // ---- epilogue ----
    if (is_r) {
        // tile 1 (cols colbase+128..+255) -> g_rh, then release both tiles.
        const int col1 = colbase + 128;
        #pragma unroll
        for (int mt = 0; mt < 4; mt++) {
            #pragma unroll
            for (int nt = 0; nt < 4; nt++) {
                int r = row0 + warp_m * 64 + mt * 16 + (lane >> 2);
                int c = col1 + warp_n * 32 + nt * 8 + (lane & 3) * 2;
                #pragma unroll
                for (int half_i = 0; half_i < 2; half_i++) {
                    size_t gi = (size_t)(r + half_i * 8) * HID + c;
                    float v0 = acc[mt][nt][half_i * 2 + 0];
                    float v1 = acc[mt][nt][half_i * 2 + 1];
                    float2 hv = *(const float2*)(h + gi);
                    *(__half2*)(g_rh + gi) = __float22half2_rn(make_float2(
                        sigmoidf_fast(v0) * hv.x, sigmoidf_fast(v1) * hv.y));
                }
            }
        }
        __threadfence();                 // release both g_rh tiles
        __syncthreads();
        if (tid == 0) atomicAdd(&g_flag[panel], 2u);
    } else {
        #pragma unroll
        for (int mt = 0; mt < 4; mt++) {
            #pragma unroll
            for (int nt = 0; nt < 4; nt++) {
                int r = row0 + warp_m * 64 + mt * 16 + (lane >> 2);
                int c = colbase + warp_n * 32 + nt * 8 + (lane & 3) * 2;
                #pragma unroll
                for (int half_i = 0; half_i < 2; half_i++) {
                    size_t gi = (size_t)(r + half_i * 8) * HID + c;
                    float v0 = acc[mt][nt][half_i * 2 + 0];
                    float v1 = acc[mt][nt][half_i * 2 + 1];
                    float2 z2  = __half22float2(*(const __half2*)(g_z + gi));
                    float2 hv2 = *(const float2*)(h + gi);
                    float t0 = tanhf_fast(v0);
                    float t1 = tanhf_fast(v1);
                    float2 o;
                    o.x = hv2.x + z2.x * (t0 - hv2.x);
                    o.y = hv2.y + z2.y * (t1 - hv2.y);
                    *(float2*)(out + gi) = o;
                }
            }
        }
    }
}

// ---------------------------------------------------------------------------

extern "C" void kernel_launch(void* const* d_in, const int* in_sizes, int n_in,
                              void* d_out, int out_size)
{
    const float* h  = (const float*)d_in[0];
    const float* x  = (const float*)d_in[1];
    const float* Wr = (const float*)d_in[2];
    const float* Wz = (const float*)d_in[3];
    const float* Wh = (const float*)d_in[4];
    float* out = (float*)d_out;

    cudaFuncSetAttribute(gru_all, cudaFuncAttributeMaxDynamicSharedMemorySize, SMEM_TOTAL);

    init_kernel<<<1, 128>>>();
    prep_concat_kernel <<<2048, 256>>>(h, x);
    dim3 gT(HID / 32, KCAT / 32, 3);
    prep_weights_kernel<<<gT, dim3(32, 8)>>>(Wr, Wz, Wh);

    gru_all<<<NBLK, 256, SMEM_TOTAL>>>(h, out);
}